// round 13
// baseline (speedup 1.0000x reference)
#include <cuda_runtime.h>

// DepthLoss3D: 48 blocks x 1024 threads, one (channel, group b) per block.
// Warps 0-7 rank-merge-sort group b (register warp sort + rank searches,
// proven in R9) while ALL threads prefetch pair p-values. Then all units
// (diag + pairs a=b+1..15) are queried in parallel, <=4 jobs/thread:
//   diag job i : sv[i] * (2i - 255)
//   pair job   : f(x)=max(x-ds,0.2ds-x,0)-0.2ds*[x<0], x=p-pb, ds>0
//     sum = n1*k1 - P[n1] + (T-P[n2]) - (256-n2)*k2 - 0.2ds*(256-n3)
// Epilogue: atomicAdd into memset-zeroed out[c] (proven fastest structure).

#define N_ELEM 4096

__device__ __forceinline__ int elem_index(int c, int g, int m) {
    if (c == 0)      return (g << 8) + m;
    else if (c == 1) return ((m >> 4) << 8) + (g << 4) + (m & 15);
    else             return (m << 4) + g;
}

__global__ void __launch_bounds__(1024) depthloss_wide(
    const float* __restrict__ pred,   // [4096,3]
    const float* __restrict__ spac,   // [3]
    float* __restrict__ out)          // [3]
{
    __shared__ float srun[8 * 33];
    __shared__ float spre[8 * 34];
    __shared__ float sv[256];
    __shared__ float sp[257];
    __shared__ float red[32];

    const int tid  = threadIdx.x;
    const int lane = tid & 31;
    const int wid  = tid >> 5;
    const int bx   = blockIdx.x;

    const int c  = bx >> 4;
    const int b  = bx & 15;
    const int nb = 16 - b;            // units: u=0 diag, u>=1 pair a=b+u
    const int njobs = nb << 8;

    const float k = spac[c] * 2.0f;

    // ---- Prefetch pair p-values for this thread's jobs (hide under sort). ----
    float pv[4];
#pragma unroll
    for (int q = 0; q < 4; ++q) {
        const int jj = tid + (q << 10);
        pv[q] = 0.0f;
        if (jj < njobs) {
            const int u = jj >> 8;
            if (u >= 1)
                pv[q] = pred[elem_index(c, b + u, jj & 255) * 3 + c];
        }
    }

    // ---- Warps 0-7: rank-merge sort of group b (R9, proven). ----
    float v = 0.0f;
    if (tid < 256) {
        v = pred[elem_index(c, b, tid) * 3 + c];

#define WSH(J, UP) do {                                             \
            const float o_ = __shfl_xor_sync(0xffffffffu, v, (J));  \
            const bool mn_ = (((lane & (J)) == 0) == (UP));         \
            v = mn_ ? fminf(v, o_) : fmaxf(v, o_);                  \
        } while (0)
        {
            const bool w2  = !(lane & 2);
            const bool w4  = !(lane & 4);
            const bool w8  = !(lane & 8);
            const bool w16 = !(lane & 16);
            WSH(1, w2);
            WSH(2, w4);  WSH(1, w4);
            WSH(4, w8);  WSH(2, w8);  WSH(1, w8);
            WSH(8, w16); WSH(4, w16); WSH(2, w16); WSH(1, w16);
            WSH(16, true); WSH(8, true); WSH(4, true); WSH(2, true); WSH(1, true);
        }
#undef WSH

        // Warp-local inclusive scan.
        float x = v;
#pragma unroll
        for (int off = 1; off < 32; off <<= 1) {
            const float y = __shfl_up_sync(0xffffffffu, x, off);
            if (lane >= off) x += y;
        }
        srun[wid * 33 + lane]     = v;
        spre[wid * 34 + lane + 1] = x;
        if (lane == 0) spre[wid * 34] = 0.0f;
    }
    __syncthreads();   // runs visible to sorting warps

    if (tid < 256) {
        // Rank + global prefix via 7 run searches (stable tie-break).
        float x = spre[wid * 34 + lane + 1];   // own inclusive prefix
        int   rank = lane;
        float pre  = x;
#pragma unroll
        for (int r = 0; r < 8; ++r) {
            if (r == wid) continue;            // warp-uniform
            const int base  = r * 33;
            const int pbase = r * 34;
            int cnt = 0;
            if (r < wid) {
#pragma unroll
                for (int s = 16; s > 0; s >>= 1)
                    cnt += (srun[base + cnt + s - 1] <= v) ? s : 0;
                cnt += (srun[base + cnt] <= v) ? 1 : 0;
            } else {
#pragma unroll
                for (int s = 16; s > 0; s >>= 1)
                    cnt += (srun[base + cnt + s - 1] < v) ? s : 0;
                cnt += (srun[base + cnt] < v) ? 1 : 0;
            }
            rank += cnt;
            pre  += spre[pbase + cnt];
        }
        sv[rank]     = v;
        sp[rank + 1] = pre;
        if (tid == 0) sp[0] = 0.0f;
    }
    __syncthreads();   // sorted array + prefix ready

    // ---- Query phase: all 1024 threads, <=4 jobs each. ----
    const float T = sp[256];
    float contrib = 0.0f;
#pragma unroll
    for (int q = 0; q < 4; ++q) {
        const int jj = tid + (q << 10);
        if (jj >= njobs) break;
        const int u = jj >> 8;
        const int i = jj & 255;
        if (u == 0) {
            contrib += sv[i] * (float)(2 * i - 255);
        } else {
            const int a = b + u;
            const float ds = (float)a * k - (float)b * k;  // ref rounding order
            const float c1 = 0.2f * ds;
            const float p  = pv[q];
            const float k1 = p - ds;
            const float k2 = p - c1;

            int cnt1 = 0, cnt2 = 0, cnt3 = 0;
#pragma unroll
            for (int s = 128; s > 0; s >>= 1) {
                cnt1 += (sv[cnt1 + s - 1] <  k1) ? s : 0;
                cnt2 += (sv[cnt2 + s - 1] <= k2) ? s : 0;
                cnt3 += (sv[cnt3 + s - 1] <= p ) ? s : 0;
            }
            cnt1 += (sv[cnt1] <  k1) ? 1 : 0;
            cnt2 += (sv[cnt2] <= k2) ? 1 : 0;
            cnt3 += (sv[cnt3] <= p ) ? 1 : 0;

            contrib += (float)cnt1 * k1 - sp[cnt1]
                     + (T - sp[cnt2]) - (float)(256 - cnt2) * k2
                     - c1 * (float)(256 - cnt3);
        }
    }

    // ---- Block reduction (32 warps) + atomic into pre-zeroed out[c]. ----
#pragma unroll
    for (int off = 16; off > 0; off >>= 1)
        contrib += __shfl_xor_sync(0xffffffffu, contrib, off);
    if (lane == 0) red[wid] = contrib;
    __syncthreads();
    if (wid == 0) {
        float tot = red[lane];
#pragma unroll
        for (int off = 16; off > 0; off >>= 1)
            tot += __shfl_xor_sync(0xffffffffu, tot, off);
        if (lane == 0)
            atomicAdd(&out[c], tot * (1.0f / ((float)N_ELEM * (float)N_ELEM)));
    }
}

extern "C" void kernel_launch(void* const* d_in, const int* in_sizes, int n_in,
                              void* d_out, int out_size)
{
    (void)in_sizes; (void)n_in; (void)out_size;
    const float* pred = (const float*)d_in[0];
    const float* spac = (const float*)d_in[1];
    float* out = (float*)d_out;

    cudaMemsetAsync(out, 0, 3 * sizeof(float));
    depthloss_wide<<<48, 1024>>>(pred, spac, out);
}

// round 14
// speedup vs baseline: 1.8351x; 1.8351x over previous
#include <cuda_runtime.h>

// DepthLoss3D: R4 hot path (best measured) + PDL-overlapped zero kernel.
// Node 1: zero_out writes out[0..2]=0, triggers programmatic completion.
// Node 2: main kernel launches concurrently (programmaticStreamSerialization);
//         each block cudaGridDependencySynchronize()s just before its single
//         atomicAdd -- by then the dependency is long satisfied (free wait).

#define N_ELEM 4096
#define NTASKS 408   // 48 diagonal + 360 pairs

__device__ __forceinline__ int elem_index(int c, int g, int m) {
    if (c == 0)      return (g << 8) + m;
    else if (c == 1) return ((m >> 4) << 8) + (g << 4) + (m & 15);
    else             return (m << 4) + g;
}

__global__ void zero_out_kernel(float* __restrict__ out) {
    if (threadIdx.x < 3) out[threadIdx.x] = 0.0f;
    cudaTriggerProgrammaticLaunchCompletion();
}

__global__ void __launch_bounds__(256) depthloss_fused(
    const float* __restrict__ pred,   // [4096,3]
    const float* __restrict__ spac,   // [3]
    float* __restrict__ out)          // [3]
{
    __shared__ float sv[256];
    __shared__ float sp[257];
    __shared__ float red[8];

    const int t    = threadIdx.x;
    const int lane = t & 31;
    const int wid  = t >> 5;
    const int bx   = blockIdx.x;

    // Task decode: bx < 48 -> diagonal (c,g); else pair (c, a>b).
    int c, a, b;
    bool diag;
    if (bx < 48) {
        diag = true;
        c = bx >> 4;
        a = b = bx & 15;
    } else {
        diag = false;
        const int idx = bx - 48;
        c = idx / 120;
        const int pq = idx - c * 120;
        a = 1;
        while ((a + 1) * a / 2 <= pq) ++a;
        b = pq - a * (a - 1) / 2;
    }

    float v = pred[elem_index(c, b, t) * 3 + c];
    float p = diag ? 0.0f : pred[elem_index(c, a, t) * 3 + c];

    // ---- Bitonic sort of v across the block (ascending by rank t). ----
    // (R4 structure, proven fastest: ptxas fully unrolls.)
#pragma unroll
    for (int k = 2; k <= 256; k <<= 1) {
        const bool up = ((t & k) == 0);
        int j = k >> 1;
        if (j >= 32) {
            sv[t] = v;
            __syncthreads();
            for (; j >= 32; j >>= 1) {
                if ((t & j) == 0) {
                    const float lo = sv[t], hi = sv[t | j];
                    if ((lo > hi) == up) { sv[t] = hi; sv[t | j] = lo; }
                }
                __syncthreads();
            }
            v = sv[t];
        }
#pragma unroll
        for (; j >= 1; j >>= 1) {
            const float other = __shfl_xor_sync(0xffffffffu, v, j);
            const bool keepMin = (((t & j) == 0) == up);
            v = keepMin ? fminf(v, other) : fmaxf(v, other);
        }
    }

    float partial;
    if (diag) {
        partial = v * (float)(2 * t - 255);
    } else {
        // Inclusive prefix scan of sorted v.
        float x = v;
#pragma unroll
        for (int off = 1; off < 32; off <<= 1) {
            const float y = __shfl_up_sync(0xffffffffu, x, off);
            if (lane >= off) x += y;
        }
        if (lane == 31) red[wid] = x;
        __syncthreads();
        float woff = 0.0f;
#pragma unroll
        for (int w = 0; w < 8; ++w)
            woff += (w < wid) ? red[w] : 0.0f;

        sv[t]     = v;
        sp[t + 1] = x + woff;
        if (t == 0) sp[0] = 0.0f;
        __syncthreads();

        // Closed form (proven):
        //   f(x)=max(x-ds,0.2ds-x,0)-0.2ds*[x<0]
        //   sum = n1*k1 - P[n1] + (T-P[n2]) - (256-n2)*k2 - 0.2ds*(256-n3)
        const float k  = spac[c] * 2.0f;
        const float ds = (float)a * k - (float)b * k;  // reference rounding order
        const float c1 = 0.2f * ds;
        const float k1 = p - ds;
        const float k2 = p - c1;

        int cnt1 = 0, cnt2 = 0, cnt3 = 0;
#pragma unroll
        for (int s = 128; s > 0; s >>= 1) {
            cnt1 += (sv[cnt1 + s - 1] <  k1) ? s : 0;
            cnt2 += (sv[cnt2 + s - 1] <= k2) ? s : 0;
            cnt3 += (sv[cnt3 + s - 1] <= p ) ? s : 0;
        }
        cnt1 += (sv[cnt1] <  k1) ? 1 : 0;
        cnt2 += (sv[cnt2] <= k2) ? 1 : 0;
        cnt3 += (sv[cnt3] <= p ) ? 1 : 0;

        const float T = sp[256];
        partial = (float)cnt1 * k1 - sp[cnt1]
                + (T - sp[cnt2]) - (float)(256 - cnt2) * k2
                - c1 * (float)(256 - cnt3);
    }

    // ---- Block reduction of partial. ----
#pragma unroll
    for (int off = 16; off > 0; off >>= 1)
        partial += __shfl_xor_sync(0xffffffffu, partial, off);
    __syncthreads();
    if (lane == 0) red[wid] = partial;
    __syncthreads();

    if (t == 0) {
        const float tot = red[0] + red[1] + red[2] + red[3]
                        + red[4] + red[5] + red[6] + red[7];
        // Wait for the zero kernel's writes to be visible (long since done).
        cudaGridDependencySynchronize();
        atomicAdd(&out[c], tot * (1.0f / ((float)N_ELEM * (float)N_ELEM)));
    }
}

extern "C" void kernel_launch(void* const* d_in, const int* in_sizes, int n_in,
                              void* d_out, int out_size)
{
    (void)in_sizes; (void)n_in; (void)out_size;
    const float* pred = (const float*)d_in[0];
    const float* spac = (const float*)d_in[1];
    float* out = (float*)d_out;

    // Node 1: zero the 3 output floats; triggers programmatic completion early.
    zero_out_kernel<<<1, 32>>>(out);

    // Node 2: main kernel with programmatic stream serialization (PDL).
    cudaLaunchConfig_t cfg = {};
    cfg.gridDim  = dim3(NTASKS, 1, 1);
    cfg.blockDim = dim3(256, 1, 1);
    cfg.dynamicSmemBytes = 0;
    cudaLaunchAttribute attrs[1];
    attrs[0].id = cudaLaunchAttributeProgrammaticStreamSerialization;
    attrs[0].val.programmaticStreamSerializationAllowed = 1;
    cfg.attrs = attrs;
    cfg.numAttrs = 1;
    cudaLaunchKernelEx(&cfg, depthloss_fused, pred, spac, out);
}